// round 5
// baseline (speedup 1.0000x reference)
#include <cuda_runtime.h>
#include <stdint.h>

// Problem constants (fixed shapes per reference_code)
#define NN 100000
#define EE 1600000
#define D  32
#define CHUNK 1024
#define NCH ((NN + CHUNK - 1) / CHUNK)   // 98
#define FULL 0xffffffffu

// ---------------- scratch (static device globals; no allocation) ----------------
__device__ int   g_deg[NN];
__device__ float g_dinv[NN];
__device__ int   g_rowptr[NN + 1];
__device__ int   g_fill[NN];
__device__ int   g_bsum[NCH];
__device__ int   g_boff[NCH];
__device__ int2  g_cw[EE];        // per (CSR-sorted) edge: {col, float_bits(weight)}
__device__ float g_h [NN * D];    // layer-1 output
__device__ float g_t1[NN * D];    // Tx1

// ---------------- build kernels ----------------
__global__ void k_zero_deg() {
    int i = blockIdx.x * blockDim.x + threadIdx.x;
    if (i < NN) g_deg[i] = 0;
}

// edge_index arrives as int32; vectorized: 4 edges per thread.
__global__ void k_hist(const int4* __restrict__ ei4) {
    int t = blockIdx.x * blockDim.x + threadIdx.x;
    if (t < EE / 4) {
        int4 r = ei4[t];
        int4 c = ei4[EE / 4 + t];
        if (r.x != c.x) atomicAdd(&g_deg[r.x], 1);
        if (r.y != c.y) atomicAdd(&g_deg[r.y], 1);
        if (r.z != c.z) atomicAdd(&g_deg[r.z], 1);
        if (r.w != c.w) atomicAdd(&g_deg[r.w], 1);
    }
}

// ---- parallel 3-phase scan (phase 1 also emits dinv) ----
__global__ void __launch_bounds__(1024) k_scan1() {
    __shared__ int warp_sums[32];
    const int tid  = threadIdx.x;
    const int lane = tid & 31;
    const int wid  = tid >> 5;
    const int i    = blockIdx.x * CHUNK + tid;
    int v = (i < NN) ? g_deg[i] : 0;
    if (i < NN) g_dinv[i] = (v > 0) ? rsqrtf((float)v) : 0.0f;
    int incl = v;
    #pragma unroll
    for (int off = 1; off < 32; off <<= 1) {
        int t = __shfl_up_sync(FULL, incl, off);
        if (lane >= off) incl += t;
    }
    if (lane == 31) warp_sums[wid] = incl;
    __syncthreads();
    if (wid == 0) {
        int s  = warp_sums[lane];
        int si = s;
        #pragma unroll
        for (int off = 1; off < 32; off <<= 1) {
            int t = __shfl_up_sync(FULL, si, off);
            if (lane >= off) si += t;
        }
        warp_sums[lane] = si - s;
        if (lane == 31) g_bsum[blockIdx.x] = si;
    }
    __syncthreads();
    int excl = warp_sums[wid] + (incl - v);
    if (i < NN) g_rowptr[i] = excl;
}

__global__ void __launch_bounds__(128) k_scan2() {
    __shared__ int warp_sums[4];
    const int tid  = threadIdx.x;
    const int lane = tid & 31;
    const int wid  = tid >> 5;
    int v = (tid < NCH) ? g_bsum[tid] : 0;
    int incl = v;
    #pragma unroll
    for (int off = 1; off < 32; off <<= 1) {
        int t = __shfl_up_sync(FULL, incl, off);
        if (lane >= off) incl += t;
    }
    if (lane == 31) warp_sums[wid] = incl;
    __syncthreads();
    int carry = 0;
    #pragma unroll
    for (int w = 0; w < 4; w++)
        if (w < wid) carry += warp_sums[w];
    int excl = carry + incl - v;
    if (tid < NCH) g_boff[tid] = excl;
    if (tid == NCH - 1) g_rowptr[NN] = excl + v;
}

__global__ void __launch_bounds__(1024) k_scan3() {
    int i = blockIdx.x * CHUNK + threadIdx.x;
    if (i < NN) {
        int val = g_rowptr[i] + g_boff[blockIdx.x];
        g_rowptr[i] = val;
        g_fill[i]   = val;
    }
}

__global__ void k_scatter(const int4* __restrict__ ei4) {
    int t = blockIdx.x * blockDim.x + threadIdx.x;
    if (t < EE / 4) {
        int4 r = ei4[t];
        int4 c = ei4[EE / 4 + t];
        #pragma unroll
        for (int q = 0; q < 4; q++) {
            int rr = (q == 0) ? r.x : (q == 1) ? r.y : (q == 2) ? r.z : r.w;
            int cc = (q == 0) ? c.x : (q == 1) ? c.y : (q == 2) ? c.z : c.w;
            if (rr != cc) {
                int pos = atomicAdd(&g_fill[rr], 1);
                float w = -g_dinv[rr] * g_dinv[cc];
                int2 cw;
                cw.x = cc;
                cw.y = __float_as_int(w);
                g_cw[pos] = cw;
            }
        }
    }
}

// ---------------- gather core: register-broadcast edge metadata ----------------
// Warp handles one row. Lane l pre-loads cw[e0+l] (covers deg<=32; rare fallback
// for deg>32). Edge (col,w) then comes via shfl -> the row-gather LDG.128s have
// no memory dependence and issue back-to-back (high MLP).
// sub = lane>>3 (edge-within-group-of-4), j = lane&7 (float4 chunk of the row).
__device__ __forceinline__ float4 gather_row(int e0, int e1, int lane, int sub, int j,
                                             const float4* __restrict__ src4) {
    float4 acc = make_float4(0.f, 0.f, 0.f, 0.f);
    const int deg = e1 - e0;
    int cwx = 0;
    float cww = 0.0f;
    if (lane < deg) {
        int2 a = g_cw[e0 + lane];
        cwx = a.x;
        cww = __int_as_float(a.y);
    }
    const int nk = (deg < 32) ? deg : 32;
    const int iters = (nk + 3) >> 2;
    for (int it = 0; it < iters; it++) {
        int k  = it * 4 + sub;
        int kk = (k < nk) ? k : (nk - 1);          // clamp: keep shfl index valid
        int   col = __shfl_sync(FULL, cwx, kk);
        float w   = __shfl_sync(FULL, cww, kk);
        if (k < nk) {
            float4 v = src4[col * 8 + j];
            acc.x = fmaf(w, v.x, acc.x); acc.y = fmaf(w, v.y, acc.y);
            acc.z = fmaf(w, v.z, acc.z); acc.w = fmaf(w, v.w, acc.w);
        }
    }
    // rare tail: deg > 32  (no warp-sync ops inside; divergence safe)
    for (int e = e0 + 32 + sub; e < e1; e += 4) {
        int2 a = g_cw[e];
        float w = __int_as_float(a.y);
        float4 v = src4[a.x * 8 + j];
        acc.x = fmaf(w, v.x, acc.x); acc.y = fmaf(w, v.y, acc.y);
        acc.z = fmaf(w, v.z, acc.z); acc.w = fmaf(w, v.w, acc.w);
    }
    return acc;
}

__device__ __forceinline__ void reduce_subs(float4& acc) {
    #pragma unroll
    for (int off = 8; off <= 16; off <<= 1) {
        acc.x += __shfl_xor_sync(FULL, acc.x, off);
        acc.y += __shfl_xor_sync(FULL, acc.y, off);
        acc.z += __shfl_xor_sync(FULL, acc.z, off);
        acc.w += __shfl_xor_sync(FULL, acc.w, off);
    }
}

// ---------------- prop1: dst = L_hat @ src ----------------
__global__ void __launch_bounds__(256) k_prop(const float4* __restrict__ src4,
                                              float4* __restrict__ dst4) {
    int row  = (blockIdx.x * blockDim.x + threadIdx.x) >> 5;
    int lane = threadIdx.x & 31;
    if (row >= NN) return;
    int sub = lane >> 3, j = lane & 7;
    int e0 = g_rowptr[row], e1 = g_rowptr[row + 1];
    float4 acc = gather_row(e0, e1, lane, sub, j, src4);
    reduce_subs(acc);
    if (lane < 8) dst4[row * 8 + lane] = acc;   // lane == j here
}

// ---------------- fused prop2 + epilogue ----------------
// p = L_hat @ t1 (in registers), then out = h0@(W0-W2) + t1@W1 + p@(2*W2) + b
__global__ void __launch_bounds__(256, 2) k_prop_epi(
        const float4* __restrict__ t1v,
        const float*  __restrict__ t1,
        const float*  __restrict__ h0,
        const float*  __restrict__ W,        // (3, 32, 32)
        const float*  __restrict__ b,
        const float*  __restrict__ resid,    // nullptr or residual rows
        float*        __restrict__ out,
        int do_relu) {
    const int lane = threadIdx.x & 31;
    const int sub  = lane >> 3, j = lane & 7;
    const int gw   = (blockIdx.x * blockDim.x + threadIdx.x) >> 5;
    const int tot  = (gridDim.x * blockDim.x) >> 5;

    // per-lane weight columns in registers
    float wc[D], w1[D], w2[D];
    #pragma unroll
    for (int i = 0; i < D; i++) {
        float a0 = W[i * D + lane];
        float a1 = W[D * D + i * D + lane];
        float a2 = W[2 * D * D + i * D + lane];
        wc[i] = a0 - a2;
        w1[i] = a1;
        w2[i] = 2.0f * a2;
    }
    const float bias = b[lane];

    for (int row = gw; row < NN; row += tot) {
        int e0 = g_rowptr[row], e1 = g_rowptr[row + 1];
        float4 acc = gather_row(e0, e1, lane, sub, j, t1v);
        reduce_subs(acc);                 // all lanes: full p chunk for j = lane&7
        float hv = h0[row * D + lane];
        float tv = t1[row * D + lane];
        float o = bias;
        #pragma unroll
        for (int i = 0; i < D; i++) {
            float hi = __shfl_sync(FULL, hv, i);
            float ti = __shfl_sync(FULL, tv, i);
            float comp = ((i & 3) == 0) ? acc.x :
                         ((i & 3) == 1) ? acc.y :
                         ((i & 3) == 2) ? acc.z : acc.w;
            float pi = __shfl_sync(FULL, comp, i >> 2);
            o = fmaf(hi, wc[i], o);
            o = fmaf(ti, w1[i], o);
            o = fmaf(pi, w2[i], o);
        }
        if (do_relu) o = fmaxf(o, 0.0f);
        if (resid)   o += resid[row * D + lane];
        out[row * D + lane] = o;
    }
}

// ---------------- launch ----------------
extern "C" void kernel_launch(void* const* d_in, const int* in_sizes, int n_in,
                              void* d_out, int out_size) {
    const float* x  = (const float*)d_in[0];
    const int*   ei = (const int*)d_in[1];       // int32 edge_index (2, E)
    const float* W1 = (const float*)d_in[2];
    const float* b1 = (const float*)d_in[3];
    const float* W2 = (const float*)d_in[4];
    const float* b2 = (const float*)d_in[5];
    float*       out = (float*)d_out;

    float *p_h, *p_t1;
    cudaGetSymbolAddress((void**)&p_h,  g_h);
    cudaGetSymbolAddress((void**)&p_t1, g_t1);

    const int TB = 256;
    int gN  = (NN + TB - 1) / TB;
    int gE4 = (EE / 4 + TB - 1) / TB;
    int gProp = (NN + 7) / 8;          // one warp per row
    int gFuse = 296;                   // 148 SMs * 2 resident CTAs

    // ---- CSR build ----
    k_zero_deg<<<gN, TB>>>();
    k_hist<<<gE4, TB>>>((const int4*)ei);
    k_scan1<<<NCH, 1024>>>();
    k_scan2<<<1, 128>>>();
    k_scan3<<<NCH, 1024>>>();
    k_scatter<<<gE4, TB>>>((const int4*)ei);

    // ---- layer 1: h = relu(cheb(x; W1,b1)) ----
    k_prop<<<gProp, TB>>>((const float4*)x, (float4*)p_t1);
    k_prop_epi<<<gFuse, TB>>>((const float4*)p_t1, p_t1, x, W1, b1,
                              (const float*)nullptr, p_h, 1);

    // ---- layer 2 + residual: out = cheb(h; W2,b2) + x ----
    k_prop<<<gProp, TB>>>((const float4*)p_h, (float4*)p_t1);
    k_prop_epi<<<gFuse, TB>>>((const float4*)p_t1, p_t1, p_h, W2, b2,
                              x, out, 0);
}

// round 6
// speedup vs baseline: 1.1162x; 1.1162x over previous
#include <cuda_runtime.h>
#include <stdint.h>

// Problem constants (fixed shapes per reference_code)
#define NN 100000
#define EE 1600000
#define D  32
#define CHUNK 1024
#define NCH ((NN + CHUNK - 1) / CHUNK)   // 98
#define FULL 0xffffffffu

// ---------------- scratch (static device globals; no allocation) ----------------
__device__ int   g_deg[NN];
__device__ float g_dinv[NN];
__device__ int   g_rowptr[NN + 1];
__device__ int   g_bsum[NCH];
__device__ int   g_boff[NCH];
__device__ int   g_rank[EE];      // per-edge rank within its row (from hist atomic)
__device__ int2  g_cw[EE];        // per (CSR-sorted) edge: {col, float_bits(weight)}
__device__ float g_h [NN * D];    // layer-1 output
__device__ float g_t1[NN * D];    // Tx1

// ---------------- build kernels ----------------
__global__ void k_zero_deg() {
    int i = blockIdx.x * blockDim.x + threadIdx.x;
    if (i < NN) g_deg[i] = 0;
}

// edge_index arrives as int32; 4 edges per thread. The atomic's return value is
// the edge's rank within its row -> saved for an atomic-free scatter later.
__global__ void k_hist(const int4* __restrict__ ei4) {
    int t = blockIdx.x * blockDim.x + threadIdx.x;
    if (t < EE / 4) {
        int4 r = ei4[t];
        int4 c = ei4[EE / 4 + t];
        int e = t * 4;
        if (r.x != c.x) g_rank[e + 0] = atomicAdd(&g_deg[r.x], 1);
        if (r.y != c.y) g_rank[e + 1] = atomicAdd(&g_deg[r.y], 1);
        if (r.z != c.z) g_rank[e + 2] = atomicAdd(&g_deg[r.z], 1);
        if (r.w != c.w) g_rank[e + 3] = atomicAdd(&g_deg[r.w], 1);
    }
}

// ---- parallel 3-phase scan (phase 1 also emits dinv) ----
__global__ void __launch_bounds__(1024) k_scan1() {
    __shared__ int warp_sums[32];
    const int tid  = threadIdx.x;
    const int lane = tid & 31;
    const int wid  = tid >> 5;
    const int i    = blockIdx.x * CHUNK + tid;
    int v = (i < NN) ? g_deg[i] : 0;
    if (i < NN) g_dinv[i] = (v > 0) ? rsqrtf((float)v) : 0.0f;
    int incl = v;
    #pragma unroll
    for (int off = 1; off < 32; off <<= 1) {
        int t = __shfl_up_sync(FULL, incl, off);
        if (lane >= off) incl += t;
    }
    if (lane == 31) warp_sums[wid] = incl;
    __syncthreads();
    if (wid == 0) {
        int s  = warp_sums[lane];
        int si = s;
        #pragma unroll
        for (int off = 1; off < 32; off <<= 1) {
            int t = __shfl_up_sync(FULL, si, off);
            if (lane >= off) si += t;
        }
        warp_sums[lane] = si - s;
        if (lane == 31) g_bsum[blockIdx.x] = si;
    }
    __syncthreads();
    int excl = warp_sums[wid] + (incl - v);
    if (i < NN) g_rowptr[i] = excl;
}

__global__ void __launch_bounds__(128) k_scan2() {
    __shared__ int warp_sums[4];
    const int tid  = threadIdx.x;
    const int lane = tid & 31;
    const int wid  = tid >> 5;
    int v = (tid < NCH) ? g_bsum[tid] : 0;
    int incl = v;
    #pragma unroll
    for (int off = 1; off < 32; off <<= 1) {
        int t = __shfl_up_sync(FULL, incl, off);
        if (lane >= off) incl += t;
    }
    if (lane == 31) warp_sums[wid] = incl;
    __syncthreads();
    int carry = 0;
    #pragma unroll
    for (int w = 0; w < 4; w++)
        if (w < wid) carry += warp_sums[w];
    int excl = carry + incl - v;
    if (tid < NCH) g_boff[tid] = excl;
    if (tid == NCH - 1) g_rowptr[NN] = excl + v;
}

__global__ void __launch_bounds__(1024) k_scan3() {
    int i = blockIdx.x * CHUNK + threadIdx.x;
    if (i < NN) g_rowptr[i] += g_boff[blockIdx.x];
}

// Atomic-free scatter: pos = rowptr[row] + rank (rank captured in k_hist)
__global__ void k_scatter(const int4* __restrict__ ei4) {
    int t = blockIdx.x * blockDim.x + threadIdx.x;
    if (t < EE / 4) {
        int4 r = ei4[t];
        int4 c = ei4[EE / 4 + t];
        int e = t * 4;
        #pragma unroll
        for (int q = 0; q < 4; q++) {
            int rr = (q == 0) ? r.x : (q == 1) ? r.y : (q == 2) ? r.z : r.w;
            int cc = (q == 0) ? c.x : (q == 1) ? c.y : (q == 2) ? c.z : c.w;
            if (rr != cc) {
                int pos = g_rowptr[rr] + g_rank[e + q];
                float w = -g_dinv[rr] * g_dinv[cc];
                int2 cw;
                cw.x = cc;
                cw.y = __float_as_int(w);
                g_cw[pos] = cw;
            }
        }
    }
}

// ---------------- gather core (R4 style, unroll 16) ----------------
// 8 lanes per edge: sub = lane>>3 picks edge within group-of-4, j = lane&7 picks
// the float4 chunk. Main loop: 16 edges/iter -> 4 cw + 4 row loads in flight/lane.
__device__ __forceinline__ float4 gather_row(int e0, int e1, int sub, int j,
                                             const float4* __restrict__ src4) {
    float4 acc = make_float4(0.f, 0.f, 0.f, 0.f);
    int e = e0 + sub;
    for (; e + 12 < e1; e += 16) {
        int2 a0 = g_cw[e];
        int2 a1 = g_cw[e + 4];
        int2 a2 = g_cw[e + 8];
        int2 a3 = g_cw[e + 12];
        float4 v0 = src4[a0.x * 8 + j];
        float4 v1 = src4[a1.x * 8 + j];
        float4 v2 = src4[a2.x * 8 + j];
        float4 v3 = src4[a3.x * 8 + j];
        float w0 = __int_as_float(a0.y);
        float w1 = __int_as_float(a1.y);
        float w2 = __int_as_float(a2.y);
        float w3 = __int_as_float(a3.y);
        acc.x = fmaf(w0, v0.x, acc.x); acc.y = fmaf(w0, v0.y, acc.y);
        acc.z = fmaf(w0, v0.z, acc.z); acc.w = fmaf(w0, v0.w, acc.w);
        acc.x = fmaf(w1, v1.x, acc.x); acc.y = fmaf(w1, v1.y, acc.y);
        acc.z = fmaf(w1, v1.z, acc.z); acc.w = fmaf(w1, v1.w, acc.w);
        acc.x = fmaf(w2, v2.x, acc.x); acc.y = fmaf(w2, v2.y, acc.y);
        acc.z = fmaf(w2, v2.z, acc.z); acc.w = fmaf(w2, v2.w, acc.w);
        acc.x = fmaf(w3, v3.x, acc.x); acc.y = fmaf(w3, v3.y, acc.y);
        acc.z = fmaf(w3, v3.z, acc.z); acc.w = fmaf(w3, v3.w, acc.w);
    }
    for (; e + 4 < e1; e += 8) {
        int2 a0 = g_cw[e];
        int2 a1 = g_cw[e + 4];
        float4 v0 = src4[a0.x * 8 + j];
        float4 v1 = src4[a1.x * 8 + j];
        float w0 = __int_as_float(a0.y);
        float w1 = __int_as_float(a1.y);
        acc.x = fmaf(w0, v0.x, acc.x); acc.y = fmaf(w0, v0.y, acc.y);
        acc.z = fmaf(w0, v0.z, acc.z); acc.w = fmaf(w0, v0.w, acc.w);
        acc.x = fmaf(w1, v1.x, acc.x); acc.y = fmaf(w1, v1.y, acc.y);
        acc.z = fmaf(w1, v1.z, acc.z); acc.w = fmaf(w1, v1.w, acc.w);
    }
    if (e < e1) {
        int2 a = g_cw[e];
        float4 v = src4[a.x * 8 + j];
        float w = __int_as_float(a.y);
        acc.x = fmaf(w, v.x, acc.x); acc.y = fmaf(w, v.y, acc.y);
        acc.z = fmaf(w, v.z, acc.z); acc.w = fmaf(w, v.w, acc.w);
    }
    return acc;
}

__device__ __forceinline__ void reduce_subs(float4& acc) {
    #pragma unroll
    for (int off = 8; off <= 16; off <<= 1) {
        acc.x += __shfl_xor_sync(FULL, acc.x, off);
        acc.y += __shfl_xor_sync(FULL, acc.y, off);
        acc.z += __shfl_xor_sync(FULL, acc.z, off);
        acc.w += __shfl_xor_sync(FULL, acc.w, off);
    }
}

// ---------------- prop1: dst = L_hat @ src ----------------
__global__ void __launch_bounds__(256) k_prop(const float4* __restrict__ src4,
                                              float4* __restrict__ dst4) {
    int row  = (blockIdx.x * blockDim.x + threadIdx.x) >> 5;
    int lane = threadIdx.x & 31;
    if (row >= NN) return;
    int sub = lane >> 3, j = lane & 7;
    int e0 = g_rowptr[row], e1 = g_rowptr[row + 1];
    float4 acc = gather_row(e0, e1, sub, j, src4);
    reduce_subs(acc);
    if (lane < 8) dst4[row * 8 + lane] = acc;   // lane == j here
}

// ---------------- fused prop2 + epilogue ----------------
// p = L_hat @ t1 (in registers), then out = h0@(W0-W2) + t1@W1 + p@(2*W2) + b
__global__ void __launch_bounds__(256, 2) k_prop_epi(
        const float4* __restrict__ t1v,
        const float*  __restrict__ t1,
        const float*  __restrict__ h0,
        const float*  __restrict__ W,        // (3, 32, 32)
        const float*  __restrict__ b,
        const float*  __restrict__ resid,    // nullptr or residual rows
        float*        __restrict__ out,
        int do_relu) {
    const int lane = threadIdx.x & 31;
    const int sub  = lane >> 3, j = lane & 7;
    const int gw   = (blockIdx.x * blockDim.x + threadIdx.x) >> 5;
    const int tot  = (gridDim.x * blockDim.x) >> 5;

    // per-lane weight columns in registers
    float wc[D], w1[D], w2[D];
    #pragma unroll
    for (int i = 0; i < D; i++) {
        float a0 = W[i * D + lane];
        float a1 = W[D * D + i * D + lane];
        float a2 = W[2 * D * D + i * D + lane];
        wc[i] = a0 - a2;
        w1[i] = a1;
        w2[i] = 2.0f * a2;
    }
    const float bias = b[lane];

    for (int row = gw; row < NN; row += tot) {
        int e0 = g_rowptr[row], e1 = g_rowptr[row + 1];
        float4 acc = gather_row(e0, e1, sub, j, t1v);
        reduce_subs(acc);                 // all lanes: full p chunk for j = lane&7
        float hv = h0[row * D + lane];
        float tv = t1[row * D + lane];
        float o = bias;
        #pragma unroll
        for (int i = 0; i < D; i++) {
            float hi = __shfl_sync(FULL, hv, i);
            float ti = __shfl_sync(FULL, tv, i);
            float comp = ((i & 3) == 0) ? acc.x :
                         ((i & 3) == 1) ? acc.y :
                         ((i & 3) == 2) ? acc.z : acc.w;
            float pi = __shfl_sync(FULL, comp, i >> 2);
            o = fmaf(hi, wc[i], o);
            o = fmaf(ti, w1[i], o);
            o = fmaf(pi, w2[i], o);
        }
        if (do_relu) o = fmaxf(o, 0.0f);
        if (resid)   o += resid[row * D + lane];
        out[row * D + lane] = o;
    }
}

// ---------------- launch ----------------
extern "C" void kernel_launch(void* const* d_in, const int* in_sizes, int n_in,
                              void* d_out, int out_size) {
    const float* x  = (const float*)d_in[0];
    const int*   ei = (const int*)d_in[1];       // int32 edge_index (2, E)
    const float* W1 = (const float*)d_in[2];
    const float* b1 = (const float*)d_in[3];
    const float* W2 = (const float*)d_in[4];
    const float* b2 = (const float*)d_in[5];
    float*       out = (float*)d_out;

    float *p_h, *p_t1;
    cudaGetSymbolAddress((void**)&p_h,  g_h);
    cudaGetSymbolAddress((void**)&p_t1, g_t1);

    const int TB = 256;
    int gN  = (NN + TB - 1) / TB;
    int gE4 = (EE / 4 + TB - 1) / TB;
    int gProp = (NN + 7) / 8;          // one warp per row
    int gFuse = 296;                   // 148 SMs * 2 resident CTAs

    // ---- CSR build ----
    k_zero_deg<<<gN, TB>>>();
    k_hist<<<gE4, TB>>>((const int4*)ei);
    k_scan1<<<NCH, 1024>>>();
    k_scan2<<<1, 128>>>();
    k_scan3<<<NCH, 1024>>>();
    k_scatter<<<gE4, TB>>>((const int4*)ei);

    // ---- layer 1: h = relu(cheb(x; W1,b1)) ----
    k_prop<<<gProp, TB>>>((const float4*)x, (float4*)p_t1);
    k_prop_epi<<<gFuse, TB>>>((const float4*)p_t1, p_t1, x, W1, b1,
                              (const float*)nullptr, p_h, 1);

    // ---- layer 2 + residual: out = cheb(h; W2,b2) + x ----
    k_prop<<<gProp, TB>>>((const float4*)p_h, (float4*)p_t1);
    k_prop_epi<<<gFuse, TB>>>((const float4*)p_t1, p_t1, p_h, W2, b2,
                              x, out, 0);
}